// round 14
// baseline (speedup 1.0000x reference)
#include <cuda_runtime.h>

// GraphAttention_14740327760460 — FINAL (held at provable floor)
//
// Dead-code analysis of the reference (verified rel_err=0.0, R1-R13):
//   Wh2 = h @ W_out is [N, 1]; log_softmax(out, axis=1) over a singleton
//   axis is x - logsumexp(x) = 0 exactly for all finite x. adj includes
//   self-loops, so every masked-softmax row is a valid distribution and
//   all intermediates are finite. The reference output is identically
//   0.0f — the full 17-GFLOP attention pipeline is dead code w.r.t. the
//   returned tensor. The minimal correct computation contains no math.
//
// Optimization ledger (predict->verify each round):
//   R2: graph memset node ~0.3us SLOWER than a kernel node -> kernel node.
//   R1/R3/R4: grid shape (16x256 scalar, 1x1024 vec, 4x256 vec) and store
//     width: NO effect on kernel GPU time — pure launch overhead.
//     DRAM=0%, L2=0.3%, all pipes=0% in all 13 profiles.
//   R4-R13: identical binary, 10 runs -> e2e {4.61,5.25,4.61,4.83,4.61,
//     4.58,4.86,6.66,4.86,4.83}us: stationary, mode 4.61, min 4.58 (x2),
//     rare clock-domain excursions (R11: kernel & e2e both +18%).
//     Residual variance is environmental, not code.
//   Rejected on theory: D2D memcpy node (CE-path class lost in R2 plus a
//     source read), node splitting (adds replay overhead), further grid
//     reshapes (model + measurements predict null).
//
// Floor: single-kernel-node graph-replay bound. Kernel: 4 blocks x 256
// threads, one STG.128 each, exact 16KB coverage, zero control flow,
// regs=16. No code lever remains.

__global__ void __launch_bounds__(256, 1)
GraphAttention_14740327760460_zero4(float4* __restrict__ out) {
    unsigned idx = blockIdx.x * 256u + threadIdx.x;
    out[idx] = make_float4(0.f, 0.f, 0.f, 0.f);
}

__global__ void GraphAttention_14740327760460_zero_generic(float* __restrict__ out, int n) {
    int i = blockIdx.x * blockDim.x + threadIdx.x;
    if (i < n) out[i] = 0.0f;
}

extern "C" void kernel_launch(void* const* d_in, const int* in_sizes, int n_in,
                              void* d_out, int out_size) {
    (void)d_in; (void)in_sizes; (void)n_in;
    if (out_size == 4096) {
        // 4096 floats = 1024 float4 = 4 blocks * 256 threads
        GraphAttention_14740327760460_zero4<<<4, 256>>>((float4*)d_out);
    } else {
        int threads = 256;
        int blocks = (out_size + threads - 1) / threads;
        GraphAttention_14740327760460_zero_generic<<<blocks, threads>>>((float*)d_out, out_size);
    }
}

// round 15
// speedup vs baseline: 1.0559x; 1.0559x over previous
#include <cuda_runtime.h>

// GraphAttention_14740327760460 — FINAL (held at provable floor)
//
// Dead-code analysis of the reference (verified rel_err=0.0, R1-R14):
//   Wh2 = h @ W_out is [N, 1]; log_softmax(out, axis=1) over a singleton
//   axis is x - logsumexp(x) = 0 exactly for all finite x. adj includes
//   self-loops, so every masked-softmax row is a valid distribution and
//   all intermediates are finite. The reference output is identically
//   0.0f — the full 17-GFLOP attention pipeline is dead code w.r.t. the
//   returned tensor. The minimal correct computation contains no math.
//
// Optimization ledger (predict->verify each round):
//   R2: graph memset node ~0.3us SLOWER than a kernel node -> kernel node.
//   R1/R3/R4: grid shape (16x256 scalar, 1x1024 vec, 4x256 vec) and store
//     width: NO effect on kernel GPU time — pure launch overhead.
//     DRAM=0%, L2=0.3%, all pipes=0% in all 14 profiles.
//   R4-R14: identical binary, 11 runs -> e2e {4.61,5.25,4.61,4.83,4.61,
//     4.58,4.86,6.66,4.86,4.83,4.83}us: stationary, mode 4.61, min 4.58
//     (x2), rare clock-domain excursions (R11: kernel & e2e both +18%).
//     Residual variance is environmental, not code.
//   Rejected on theory: D2D memcpy node (CE-path class lost in R2 plus a
//     source read), node splitting (adds replay overhead), further grid
//     reshapes (model + measurements predict null).
//
// Floor: single-kernel-node graph-replay bound. Kernel: 4 blocks x 256
// threads, one STG.128 each, exact 16KB coverage, zero control flow,
// regs=16. No code lever remains; sub-4.58 would require a cheaper
// graph-node dispatch than a minimal kernel launch, which this stack
// does not offer.

__global__ void __launch_bounds__(256, 1)
GraphAttention_14740327760460_zero4(float4* __restrict__ out) {
    unsigned idx = blockIdx.x * 256u + threadIdx.x;
    out[idx] = make_float4(0.f, 0.f, 0.f, 0.f);
}

__global__ void GraphAttention_14740327760460_zero_generic(float* __restrict__ out, int n) {
    int i = blockIdx.x * blockDim.x + threadIdx.x;
    if (i < n) out[i] = 0.0f;
}

extern "C" void kernel_launch(void* const* d_in, const int* in_sizes, int n_in,
                              void* d_out, int out_size) {
    (void)d_in; (void)in_sizes; (void)n_in;
    if (out_size == 4096) {
        // 4096 floats = 1024 float4 = 4 blocks * 256 threads
        GraphAttention_14740327760460_zero4<<<4, 256>>>((float4*)d_out);
    } else {
        int threads = 256;
        int blocks = (out_size + threads - 1) / threads;
        GraphAttention_14740327760460_zero_generic<<<blocks, threads>>>((float*)d_out, out_size);
    }
}